// round 1
// baseline (speedup 1.0000x reference)
#include <cuda_runtime.h>

#define NPTS   8192
#define BATCH  4
#define M      2048
#define KNN    32
#define CF     32
#define R2     0.04f

// scratch (no allocations allowed)
__device__ int g_idx[BATCH * M * KNN];
__device__ int g_cidx[BATCH * M];

// ---------------------------------------------------------------------------
// Kernel 1: furthest point sampling. One block per batch, 1024 threads,
// 8 points per thread held in registers. Block argmax via packed u64 keys
// (float bits << 32 | inverted index) so ties resolve to the lowest index,
// matching jnp.argmax.
// ---------------------------------------------------------------------------
__global__ __launch_bounds__(1024, 1) void fps_kernel(
    const float* __restrict__ coords, float* __restrict__ centers)
{
    const int b = blockIdx.x, tid = threadIdx.x;
    const int wid = tid >> 5, lane = tid & 31;
    const float* X = coords + (size_t)b * 3 * NPTS;
    const float* Y = X + NPTS;
    const float* Z = X + 2 * NPTS;

    float px[8], py[8], pz[8], d[8];
#pragma unroll
    for (int i = 0; i < 8; i++) {
        int n = tid + i * 1024;
        px[i] = X[n]; py[i] = Y[n]; pz[i] = Z[n];
        d[i] = 1e30f;   // coords in [0,1): any real dist <= 3, acts as +inf
    }

    __shared__ unsigned long long wbest[32];
    __shared__ float fx, fy, fz;

    float* ox = centers + (size_t)b * 3 * M;
    float* oy = ox + M;
    float* oz = ox + 2 * M;

    if (tid == 0) {
        g_cidx[b * M] = 0;
        float a = X[0], bb = Y[0], cc = Z[0];
        ox[0] = a; oy[0] = bb; oz[0] = cc;
        fx = a; fy = bb; fz = cc;
    }
    __syncthreads();

    for (int s = 0; s < M; s++) {
        const float cx = fx, cy = fy, cz = fz;
        float bm = -1.0f;
        int   bi = 0;
#pragma unroll
        for (int i = 0; i < 8; i++) {
            float dx = px[i] - cx, dy = py[i] - cy, dz = pz[i] - cz;
            float dd = fmaf(dz, dz, fmaf(dy, dy, dx * dx));
            dd = fminf(d[i], dd);
            d[i] = dd;
            if (dd > bm) { bm = dd; bi = tid + i * 1024; }  // strict >: lowest idx wins
        }
        unsigned long long key =
            ((unsigned long long)__float_as_uint(bm) << 32) |
            (unsigned)(NPTS - 1 - bi);
#pragma unroll
        for (int off = 16; off; off >>= 1) {
            unsigned long long o = __shfl_down_sync(0xffffffffu, key, off);
            key = (o > key) ? o : key;
        }
        if (lane == 0) wbest[wid] = key;
        __syncthreads();
        if (wid == 0) {
            key = wbest[lane];
#pragma unroll
            for (int off = 16; off; off >>= 1) {
                unsigned long long o = __shfl_down_sync(0xffffffffu, key, off);
                key = (o > key) ? o : key;
            }
            if (lane == 0 && s + 1 < M) {
                int idx = NPTS - 1 - (int)(key & 0xffffffffu);
                float a = X[idx], bb = Y[idx], cc = Z[idx];
                g_cidx[b * M + s + 1] = idx;
                ox[s + 1] = a; oy[s + 1] = bb; oz[s + 1] = cc;
                fx = a; fy = bb; fz = cc;
            }
        }
        __syncthreads();
    }
}

// ---------------------------------------------------------------------------
// Kernel 2: ball query. One warp per center. Scans points in ascending index
// order, ballot-compacts hits, stops after K hits (== sorted-keys-take-k).
// Pads with the first hit index (0 if no hit), matching the reference.
// ---------------------------------------------------------------------------
__global__ __launch_bounds__(256) void bq_kernel(
    const float* __restrict__ coords, const float* __restrict__ centers)
{
    const int gw   = (blockIdx.x * blockDim.x + threadIdx.x) >> 5;
    const int lane = threadIdx.x & 31;
    if (gw >= BATCH * M) return;
    const int b = gw >> 11, m = gw & (M - 1);

    const float* X = coords + (size_t)b * 3 * NPTS;
    const float* Y = X + NPTS;
    const float* Z = X + 2 * NPTS;
    const float* C = centers + (size_t)b * 3 * M;
    const float cx = C[m], cy = C[M + m], cz = C[2 * M + m];

    const int base = gw * KNN;
    int cnt = 0, firstn = 0;

    for (int c0 = 0; c0 < NPTS; c0 += 32) {
        const int n = c0 + lane;
        float dx = X[n] - cx, dy = Y[n] - cy, dz = Z[n] - cz;
        float d2 = fmaf(dz, dz, fmaf(dy, dy, dx * dx));
        bool hit = d2 < R2;
        unsigned mask = __ballot_sync(0xffffffffu, hit);
        if (cnt == 0 && mask) firstn = c0 + __ffs(mask) - 1;
        int pos = cnt + __popc(mask & ((1u << lane) - 1u));
        if (hit && pos < KNN) g_idx[base + pos] = n;
        cnt += __popc(mask);
        if (cnt >= KNN) break;
    }
    for (int j = cnt + lane; j < KNN; j += 32) g_idx[base + j] = firstn;
}

// ---------------------------------------------------------------------------
// Kernel 3: gather + 3-layer MLP + max-pool. Warp = center, lane = neighbor.
// Weights transposed in SMEM -> 1 LDS.128 + 4 FFMA per k-step.
// Maxpool over k=32 == warp butterfly reduce per output channel.
// ---------------------------------------------------------------------------
__global__ __launch_bounds__(256, 1) void mlp_kernel(
    const float* __restrict__ coords, const float* __restrict__ feats,
    const float* __restrict__ W1, const float* __restrict__ B1,
    const float* __restrict__ W2, const float* __restrict__ B2,
    const float* __restrict__ W3, const float* __restrict__ B3,
    const float* __restrict__ centers, float* __restrict__ out)
{
    extern __shared__ float sm[];
    float* w1t = sm;                   // [35][64]  w1t[c*64+o] = W1[o*35+c]
    float* w2t = w1t + 35 * 64;        // [64][64]
    float* w3t = w2t + 64 * 64;        // [64][128]
    float* sb1 = w3t + 64 * 128;
    float* sb2 = sb1 + 64;
    float* sb3 = sb2 + 64;

    const int tid = threadIdx.x;
    for (int i = tid; i < 35 * 64; i += 256) { int c = i >> 6, o = i & 63;  w1t[i] = W1[o * 35 + c]; }
    for (int i = tid; i < 64 * 64; i += 256) { int c = i >> 6, o = i & 63;  w2t[i] = W2[o * 64 + c]; }
    for (int i = tid; i < 64 * 128; i += 256){ int c = i >> 7, o = i & 127; w3t[i] = W3[o * 64 + c]; }
    if (tid < 64)  sb1[tid] = B1[tid];
    if (tid < 64)  sb2[tid] = B2[tid];
    if (tid < 128) sb3[tid] = B3[tid];
    __syncthreads();

    const int wid = tid >> 5, lane = tid & 31;
    const int gw = blockIdx.x * 8 + wid;
    const int b = gw >> 11, m = gw & (M - 1);

    const int idx = g_idx[gw * KNN + lane];
    const float* X = coords + (size_t)b * 3 * NPTS;
    const float* F = feats + (size_t)b * CF * NPTS;
    const float* C = centers + (size_t)b * 3 * M;

    float in[35];
    in[0] = X[idx]            - C[m];
    in[1] = X[NPTS + idx]     - C[M + m];
    in[2] = X[2 * NPTS + idx] - C[2 * M + m];
#pragma unroll
    for (int c = 0; c < CF; c++) in[3 + c] = F[c * NPTS + idx];

    // Layer 1: 35 -> 64
    float h1[64];
#pragma unroll
    for (int og = 0; og < 64; og += 4) {
        float a0 = sb1[og], a1 = sb1[og + 1], a2 = sb1[og + 2], a3 = sb1[og + 3];
#pragma unroll
        for (int c = 0; c < 35; c++) {
            const float4 w = *(const float4*)(w1t + c * 64 + og);
            const float x = in[c];
            a0 = fmaf(w.x, x, a0); a1 = fmaf(w.y, x, a1);
            a2 = fmaf(w.z, x, a2); a3 = fmaf(w.w, x, a3);
        }
        h1[og] = fmaxf(a0, 0.f); h1[og + 1] = fmaxf(a1, 0.f);
        h1[og + 2] = fmaxf(a2, 0.f); h1[og + 3] = fmaxf(a3, 0.f);
    }

    // Layer 2: 64 -> 64
    float h2[64];
#pragma unroll
    for (int og = 0; og < 64; og += 4) {
        float a0 = sb2[og], a1 = sb2[og + 1], a2 = sb2[og + 2], a3 = sb2[og + 3];
#pragma unroll
        for (int c = 0; c < 64; c++) {
            const float4 w = *(const float4*)(w2t + c * 64 + og);
            const float x = h1[c];
            a0 = fmaf(w.x, x, a0); a1 = fmaf(w.y, x, a1);
            a2 = fmaf(w.z, x, a2); a3 = fmaf(w.w, x, a3);
        }
        h2[og] = fmaxf(a0, 0.f); h2[og + 1] = fmaxf(a1, 0.f);
        h2[og + 2] = fmaxf(a2, 0.f); h2[og + 3] = fmaxf(a3, 0.f);
    }

    // Layer 3: 64 -> 128, relu, warp-max over k, lane0 writes
    float* O = out + (size_t)b * 128 * M + m;
#pragma unroll
    for (int og = 0; og < 128; og += 4) {
        float a0 = sb3[og], a1 = sb3[og + 1], a2 = sb3[og + 2], a3 = sb3[og + 3];
#pragma unroll
        for (int c = 0; c < 64; c++) {
            const float4 w = *(const float4*)(w3t + c * 128 + og);
            const float x = h2[c];
            a0 = fmaf(w.x, x, a0); a1 = fmaf(w.y, x, a1);
            a2 = fmaf(w.z, x, a2); a3 = fmaf(w.w, x, a3);
        }
        a0 = fmaxf(a0, 0.f); a1 = fmaxf(a1, 0.f);
        a2 = fmaxf(a2, 0.f); a3 = fmaxf(a3, 0.f);
#pragma unroll
        for (int off = 16; off; off >>= 1) {
            a0 = fmaxf(a0, __shfl_xor_sync(0xffffffffu, a0, off));
            a1 = fmaxf(a1, __shfl_xor_sync(0xffffffffu, a1, off));
            a2 = fmaxf(a2, __shfl_xor_sync(0xffffffffu, a2, off));
            a3 = fmaxf(a3, __shfl_xor_sync(0xffffffffu, a3, off));
        }
        if (lane == 0) {
            O[(og + 0) * M] = a0; O[(og + 1) * M] = a1;
            O[(og + 2) * M] = a2; O[(og + 3) * M] = a3;
        }
    }
}

// ---------------------------------------------------------------------------
// Launch: out layout = [out (B,128,M)] then [centers (B,3,M)]
// ---------------------------------------------------------------------------
extern "C" void kernel_launch(void* const* d_in, const int* in_sizes, int n_in,
                              void* d_out, int out_size)
{
    const float* feats  = (const float*)d_in[0];
    const float* coords = (const float*)d_in[1];
    const float* W1 = (const float*)d_in[2];
    const float* B1 = (const float*)d_in[3];
    const float* W2 = (const float*)d_in[4];
    const float* B2 = (const float*)d_in[5];
    const float* W3 = (const float*)d_in[6];
    const float* B3 = (const float*)d_in[7];

    float* out     = (float*)d_out;
    float* centers = out + (size_t)BATCH * 128 * M;

    fps_kernel<<<BATCH, 1024>>>(coords, centers);

    bq_kernel<<<(BATCH * M) / 8, 256>>>(coords, centers);

    const int SMEM = (35 * 64 + 64 * 64 + 64 * 128 + 64 + 64 + 128) * 4;
    cudaFuncSetAttribute(mlp_kernel, cudaFuncAttributeMaxDynamicSharedMemorySize, SMEM);
    mlp_kernel<<<(BATCH * M) / 8, 256, SMEM>>>(
        coords, feats, W1, B1, W2, B2, W3, B3, centers, out);
}

// round 2
// speedup vs baseline: 1.2709x; 1.2709x over previous
#include <cuda_runtime.h>

#define NPTS   8192
#define BATCH  4
#define M      2048
#define KNN    32
#define CF     32
#define R2     0.04f

typedef unsigned long long ull;

// scratch (no allocations allowed)
__device__ int g_idx[BATCH * M * KNN];

// ---- packed f32x2 helpers (bit-identical IEEE f32 per lane) ----------------
__device__ __forceinline__ ull f2pack(float a, float b) {
    ull r; asm("mov.b64 %0, {%1,%2};" : "=l"(r) : "f"(a), "f"(b)); return r;
}
__device__ __forceinline__ void f2unpack(ull v, float& a, float& b) {
    asm("mov.b64 {%0,%1}, %2;" : "=f"(a), "=f"(b) : "l"(v));
}
#define F2ADD(d, a, b)    asm("add.rn.f32x2 %0, %1, %2;"     : "=l"(d) : "l"(a), "l"(b))
#define F2MUL(d, a, b)    asm("mul.rn.f32x2 %0, %1, %2;"     : "=l"(d) : "l"(a), "l"(b))
#define F2FMA(d, a, b, c) asm("fma.rn.f32x2 %0, %1, %2, %3;" : "=l"(d) : "l"(a), "l"(b), "l"(c))

__device__ __forceinline__ unsigned redux_max_u32(unsigned v) {
    unsigned r; asm("redux.sync.max.u32 %0, %1, 0xffffffff;" : "=r"(r) : "r"(v)); return r;
}
__device__ __forceinline__ unsigned redux_min_u32(unsigned v) {
    unsigned r; asm("redux.sync.min.u32 %0, %1, 0xffffffff;" : "=r"(r) : "r"(v)); return r;
}

// ---------------------------------------------------------------------------
// Kernel 1: furthest point sampling. One block per batch, 1024 threads,
// 8 points per thread (4 f32x2 pairs) in registers. Distance math is the
// exact (p-c)^2 form (same rounding as the scalar reference path). Exact
// lowest-global-index tie-break at every reduction level via
// redux.max(distance bits) + redux.min(masked index).
// ---------------------------------------------------------------------------
__global__ __launch_bounds__(1024, 1) void fps_kernel(
    const float* __restrict__ coords, float* __restrict__ centers)
{
    const int b = blockIdx.x, tid = threadIdx.x;
    const int wid = tid >> 5, lane = tid & 31;
    const float* X = coords + (size_t)b * 3 * NPTS;
    const float* Y = X + NPTS;
    const float* Z = X + 2 * NPTS;

    ull px2[4], py2[4], pz2[4];
    float dl[8];
#pragma unroll
    for (int j = 0; j < 4; j++) {
        int n0 = tid + (2 * j) * 1024, n1 = tid + (2 * j + 1) * 1024;
        px2[j] = f2pack(X[n0], X[n1]);
        py2[j] = f2pack(Y[n0], Y[n1]);
        pz2[j] = f2pack(Z[n0], Z[n1]);
        dl[2 * j] = 1e30f; dl[2 * j + 1] = 1e30f;
    }

    __shared__ unsigned swv[32];
    __shared__ int      swi[32];
    __shared__ float fx, fy, fz;

    float* ox = centers + (size_t)b * 3 * M;
    float* oy = ox + M;
    float* oz = ox + 2 * M;

    if (tid == 0) {
        float a = X[0], bb = Y[0], cc = Z[0];
        ox[0] = a; oy[0] = bb; oz[0] = cc;
        fx = a; fy = bb; fz = cc;
    }
    __syncthreads();

    for (int s = 0; s < M; s++) {
        const float cx = fx, cy = fy, cz = fz;
        const ull ncx = f2pack(-cx, -cx);
        const ull ncy = f2pack(-cy, -cy);
        const ull ncz = f2pack(-cz, -cz);

        float bm = -1.0f;
        int bp = 0;
#pragma unroll
        for (int j = 0; j < 4; j++) {
            ull dx, dy, dz, t;
            F2ADD(dx, px2[j], ncx);
            F2ADD(dy, py2[j], ncy);
            F2ADD(dz, pz2[j], ncz);
            F2MUL(t, dx, dx);
            F2FMA(t, dy, dy, t);
            F2FMA(t, dz, dz, t);
            float t0, t1; f2unpack(t, t0, t1);
            float d0 = fminf(dl[2 * j],     t0); dl[2 * j]     = d0;
            float d1 = fminf(dl[2 * j + 1], t1); dl[2 * j + 1] = d1;
            float m = fmaxf(d0, d1);
            if (m > bm) { bm = m; bp = j; }   // strict >: lowest pair wins
        }
        // lowest-index disambiguation inside the winning pair (exact)
        int bi = (dl[2 * bp] == bm) ? (tid + (2 * bp) * 1024)
                                    : (tid + (2 * bp + 1) * 1024);

        // warp reduce: max distance bits, then min global index among ties
        unsigned mb = __float_as_uint(bm);          // bm >= 0 -> monotone bits
        unsigned wm = redux_max_u32(mb);
        unsigned ci = (mb == wm) ? (unsigned)bi : 0x7fffffffu;
        unsigned wi = redux_min_u32(ci);
        if (lane == 0) { swv[wid] = wm; swi[wid] = (int)wi; }
        __syncthreads();

        if (wid == 0) {
            unsigned v = swv[lane];
            int     ii = swi[lane];
            unsigned gm = redux_max_u32(v);
            unsigned c2 = (v == gm) ? (unsigned)ii : 0x7fffffffu;
            unsigned gi = redux_min_u32(c2);
            if (lane == 0 && s + 1 < M) {
                float a = X[gi], bb = Y[gi], cc = Z[gi];
                ox[s + 1] = a; oy[s + 1] = bb; oz[s + 1] = cc;
                fx = a; fy = bb; fz = cc;
            }
        }
        __syncthreads();
    }
}

// ---------------------------------------------------------------------------
// Kernel 2: ball query. One warp per center. Scans points in ascending index
// order, ballot-compacts hits, stops after K hits (== sorted-keys-take-k).
// Pads with the first hit index (0 if none), matching the reference.
// ---------------------------------------------------------------------------
__global__ __launch_bounds__(256) void bq_kernel(
    const float* __restrict__ coords, const float* __restrict__ centers)
{
    const int gw   = (blockIdx.x * blockDim.x + threadIdx.x) >> 5;
    const int lane = threadIdx.x & 31;
    if (gw >= BATCH * M) return;
    const int b = gw >> 11, m = gw & (M - 1);

    const float* X = coords + (size_t)b * 3 * NPTS;
    const float* Y = X + NPTS;
    const float* Z = X + 2 * NPTS;
    const float* C = centers + (size_t)b * 3 * M;
    const float cx = C[m], cy = C[M + m], cz = C[2 * M + m];

    const int base = gw * KNN;
    int cnt = 0, firstn = 0;

    for (int c0 = 0; c0 < NPTS; c0 += 32) {
        const int n = c0 + lane;
        float dx = X[n] - cx, dy = Y[n] - cy, dz = Z[n] - cz;
        float d2 = fmaf(dz, dz, fmaf(dy, dy, dx * dx));
        bool hit = d2 < R2;
        unsigned mask = __ballot_sync(0xffffffffu, hit);
        if (cnt == 0 && mask) firstn = c0 + __ffs(mask) - 1;
        int pos = cnt + __popc(mask & ((1u << lane) - 1u));
        if (hit && pos < KNN) g_idx[base + pos] = n;
        cnt += __popc(mask);
        if (cnt >= KNN) break;
    }
    for (int j = cnt + lane; j < KNN; j += 32) g_idx[base + j] = firstn;
}

// ---------------------------------------------------------------------------
// Kernel 3: gather + 3-layer MLP + max-pool. Warp = center, lane = neighbor.
// Weights transposed in SMEM -> 1 LDS.128 + 4 FFMA per k-step.
// Maxpool over k=32 == warp butterfly reduce per output channel.
// ---------------------------------------------------------------------------
__global__ __launch_bounds__(256, 1) void mlp_kernel(
    const float* __restrict__ coords, const float* __restrict__ feats,
    const float* __restrict__ W1, const float* __restrict__ B1,
    const float* __restrict__ W2, const float* __restrict__ B2,
    const float* __restrict__ W3, const float* __restrict__ B3,
    const float* __restrict__ centers, float* __restrict__ out)
{
    extern __shared__ float sm[];
    float* w1t = sm;                   // [35][64]
    float* w2t = w1t + 35 * 64;        // [64][64]
    float* w3t = w2t + 64 * 64;        // [64][128]
    float* sb1 = w3t + 64 * 128;
    float* sb2 = sb1 + 64;
    float* sb3 = sb2 + 64;

    const int tid = threadIdx.x;
    for (int i = tid; i < 35 * 64; i += 256) { int c = i >> 6, o = i & 63;  w1t[i] = W1[o * 35 + c]; }
    for (int i = tid; i < 64 * 64; i += 256) { int c = i >> 6, o = i & 63;  w2t[i] = W2[o * 64 + c]; }
    for (int i = tid; i < 64 * 128; i += 256){ int c = i >> 7, o = i & 127; w3t[i] = W3[o * 64 + c]; }
    if (tid < 64)  sb1[tid] = B1[tid];
    if (tid < 64)  sb2[tid] = B2[tid];
    if (tid < 128) sb3[tid] = B3[tid];
    __syncthreads();

    const int wid = tid >> 5, lane = tid & 31;
    const int gw = blockIdx.x * 8 + wid;
    const int b = gw >> 11, m = gw & (M - 1);

    const int idx = g_idx[gw * KNN + lane];
    const float* X = coords + (size_t)b * 3 * NPTS;
    const float* F = feats + (size_t)b * CF * NPTS;
    const float* C = centers + (size_t)b * 3 * M;

    float in[35];
    in[0] = X[idx]            - C[m];
    in[1] = X[NPTS + idx]     - C[M + m];
    in[2] = X[2 * NPTS + idx] - C[2 * M + m];
#pragma unroll
    for (int c = 0; c < CF; c++) in[3 + c] = F[c * NPTS + idx];

    float h1[64];
#pragma unroll
    for (int og = 0; og < 64; og += 4) {
        float a0 = sb1[og], a1 = sb1[og + 1], a2 = sb1[og + 2], a3 = sb1[og + 3];
#pragma unroll
        for (int c = 0; c < 35; c++) {
            const float4 w = *(const float4*)(w1t + c * 64 + og);
            const float x = in[c];
            a0 = fmaf(w.x, x, a0); a1 = fmaf(w.y, x, a1);
            a2 = fmaf(w.z, x, a2); a3 = fmaf(w.w, x, a3);
        }
        h1[og] = fmaxf(a0, 0.f); h1[og + 1] = fmaxf(a1, 0.f);
        h1[og + 2] = fmaxf(a2, 0.f); h1[og + 3] = fmaxf(a3, 0.f);
    }

    float h2[64];
#pragma unroll
    for (int og = 0; og < 64; og += 4) {
        float a0 = sb2[og], a1 = sb2[og + 1], a2 = sb2[og + 2], a3 = sb2[og + 3];
#pragma unroll
        for (int c = 0; c < 64; c++) {
            const float4 w = *(const float4*)(w2t + c * 64 + og);
            const float x = h1[c];
            a0 = fmaf(w.x, x, a0); a1 = fmaf(w.y, x, a1);
            a2 = fmaf(w.z, x, a2); a3 = fmaf(w.w, x, a3);
        }
        h2[og] = fmaxf(a0, 0.f); h2[og + 1] = fmaxf(a1, 0.f);
        h2[og + 2] = fmaxf(a2, 0.f); h2[og + 3] = fmaxf(a3, 0.f);
    }

    float* O = out + (size_t)b * 128 * M + m;
#pragma unroll
    for (int og = 0; og < 128; og += 4) {
        float a0 = sb3[og], a1 = sb3[og + 1], a2 = sb3[og + 2], a3 = sb3[og + 3];
#pragma unroll
        for (int c = 0; c < 64; c++) {
            const float4 w = *(const float4*)(w3t + c * 128 + og);
            const float x = h2[c];
            a0 = fmaf(w.x, x, a0); a1 = fmaf(w.y, x, a1);
            a2 = fmaf(w.z, x, a2); a3 = fmaf(w.w, x, a3);
        }
        a0 = fmaxf(a0, 0.f); a1 = fmaxf(a1, 0.f);
        a2 = fmaxf(a2, 0.f); a3 = fmaxf(a3, 0.f);
#pragma unroll
        for (int off = 16; off; off >>= 1) {
            a0 = fmaxf(a0, __shfl_xor_sync(0xffffffffu, a0, off));
            a1 = fmaxf(a1, __shfl_xor_sync(0xffffffffu, a1, off));
            a2 = fmaxf(a2, __shfl_xor_sync(0xffffffffu, a2, off));
            a3 = fmaxf(a3, __shfl_xor_sync(0xffffffffu, a3, off));
        }
        if (lane == 0) {
            O[(og + 0) * M] = a0; O[(og + 1) * M] = a1;
            O[(og + 2) * M] = a2; O[(og + 3) * M] = a3;
        }
    }
}

// ---------------------------------------------------------------------------
extern "C" void kernel_launch(void* const* d_in, const int* in_sizes, int n_in,
                              void* d_out, int out_size)
{
    const float* feats  = (const float*)d_in[0];
    const float* coords = (const float*)d_in[1];
    const float* W1 = (const float*)d_in[2];
    const float* B1 = (const float*)d_in[3];
    const float* W2 = (const float*)d_in[4];
    const float* B2 = (const float*)d_in[5];
    const float* W3 = (const float*)d_in[6];
    const float* B3 = (const float*)d_in[7];

    float* out     = (float*)d_out;
    float* centers = out + (size_t)BATCH * 128 * M;

    fps_kernel<<<BATCH, 1024>>>(coords, centers);

    bq_kernel<<<(BATCH * M) / 8, 256>>>(coords, centers);

    const int SMEM = (35 * 64 + 64 * 64 + 64 * 128 + 64 + 64 + 128) * 4;
    cudaFuncSetAttribute(mlp_kernel, cudaFuncAttributeMaxDynamicSharedMemorySize, SMEM);
    mlp_kernel<<<(BATCH * M) / 8, 256, SMEM>>>(
        coords, feats, W1, B1, W2, B2, W3, B3, centers, out);
}

// round 3
// speedup vs baseline: 1.3180x; 1.0370x over previous
#include <cuda_runtime.h>

#define NPTS   8192
#define BATCH  4
#define M      2048
#define KNN    32
#define CF     32
#define R2     0.04f

typedef unsigned long long ull;

// scratch (no allocations allowed)
__device__ int   g_idx[BATCH * M * KNN];
#define WTOT (35*64 + 64*64 + 64*128 + 64 + 64 + 128)   // 14784
__device__ float g_w[WTOT];

// ---- packed f32x2 helpers (bit-identical IEEE f32 per lane) ----------------
__device__ __forceinline__ ull f2pack(float a, float b) {
    ull r; asm("mov.b64 %0, {%1,%2};" : "=l"(r) : "f"(a), "f"(b)); return r;
}
__device__ __forceinline__ void f2unpack(ull v, float& a, float& b) {
    asm("mov.b64 {%0,%1}, %2;" : "=f"(a), "=f"(b) : "l"(v));
}
#define F2ADD(d, a, b)    asm("add.rn.f32x2 %0, %1, %2;"     : "=l"(d) : "l"(a), "l"(b))
#define F2MUL(d, a, b)    asm("mul.rn.f32x2 %0, %1, %2;"     : "=l"(d) : "l"(a), "l"(b))
#define F2FMA(d, a, b, c) asm("fma.rn.f32x2 %0, %1, %2, %3;" : "=l"(d) : "l"(a), "l"(b), "l"(c))

__device__ __forceinline__ unsigned redux_max_u32(unsigned v) {
    unsigned r; asm("redux.sync.max.u32 %0, %1, 0xffffffff;" : "=r"(r) : "r"(v)); return r;
}
__device__ __forceinline__ unsigned redux_min_u32(unsigned v) {
    unsigned r; asm("redux.sync.min.u32 %0, %1, 0xffffffff;" : "=r"(r) : "r"(v)); return r;
}

// ---------------------------------------------------------------------------
// Kernel 1: furthest point sampling. One block per batch, 1024 threads,
// 8 points per thread (4 f32x2 pairs) in registers.
// ONE barrier per iteration: warps publish packed (dist_bits<<32 | min_idx)
// keys to a double-buffered smem array; after the barrier EVERY warp
// redundantly reduces the 32 keys (redux.max on dist bits, redux.min on
// masked index = exact lowest-index tie-break) and loads the next centroid
// itself via a lane-invariant L1 broadcast load. No second barrier needed:
// buffer p is only rewritten after the next barrier, which all readers of
// p have also passed.
// ---------------------------------------------------------------------------
__global__ __launch_bounds__(1024, 1) void fps_kernel(
    const float* __restrict__ coords, float* __restrict__ centers)
{
    const int b = blockIdx.x, tid = threadIdx.x;
    const int wid = tid >> 5, lane = tid & 31;
    const float* X = coords + (size_t)b * 3 * NPTS;
    const float* Y = X + NPTS;
    const float* Z = X + 2 * NPTS;

    ull px2[4], py2[4], pz2[4];
    float dl[8];
#pragma unroll
    for (int j = 0; j < 4; j++) {
        int n0 = tid + (2 * j) * 1024, n1 = tid + (2 * j + 1) * 1024;
        px2[j] = f2pack(X[n0], X[n1]);
        py2[j] = f2pack(Y[n0], Y[n1]);
        pz2[j] = f2pack(Z[n0], Z[n1]);
        dl[2 * j] = 1e30f; dl[2 * j + 1] = 1e30f;
    }

    __shared__ ull skey[2][32];

    float* ox = centers + (size_t)b * 3 * M;
    float* oy = ox + M;
    float* oz = ox + 2 * M;

    float cx = __ldg(X), cy = __ldg(Y), cz = __ldg(Z);
    if (tid == 0) { ox[0] = cx; oy[0] = cy; oz[0] = cz; }

    for (int s = 0; s < M; s++) {
        const ull ncx = f2pack(-cx, -cx);
        const ull ncy = f2pack(-cy, -cy);
        const ull ncz = f2pack(-cz, -cz);

        float bm = -1.0f;
        int bp = 0;
#pragma unroll
        for (int j = 0; j < 4; j++) {
            ull dx, dy, dz, t;
            F2ADD(dx, px2[j], ncx);
            F2ADD(dy, py2[j], ncy);
            F2ADD(dz, pz2[j], ncz);
            F2MUL(t, dx, dx);
            F2FMA(t, dy, dy, t);
            F2FMA(t, dz, dz, t);
            float t0, t1; f2unpack(t, t0, t1);
            float d0 = fminf(dl[2 * j],     t0); dl[2 * j]     = d0;
            float d1 = fminf(dl[2 * j + 1], t1); dl[2 * j + 1] = d1;
            float m = fmaxf(d0, d1);
            if (m > bm) { bm = m; bp = j; }   // strict >: lowest pair wins
        }
        // lowest-index disambiguation inside the winning pair (exact)
        int bi = (dl[2 * bp] == bm) ? (tid + (2 * bp) * 1024)
                                    : (tid + (2 * bp + 1) * 1024);

        // warp reduce: max distance bits, then min global index among ties
        unsigned mb = __float_as_uint(bm);          // bm >= 0 -> monotone bits
        unsigned wm = redux_max_u32(mb);
        unsigned ci = (mb == wm) ? (unsigned)bi : 0x7fffffffu;
        unsigned wi = redux_min_u32(ci);
        if (lane == 0) skey[s & 1][wid] = ((ull)wm << 32) | wi;
        __syncthreads();

        // stage 2: every warp reduces the 32 warp keys redundantly
        ull k = skey[s & 1][lane];
        unsigned v  = (unsigned)(k >> 32);
        unsigned ii = (unsigned)k;
        unsigned gm = redux_max_u32(v);
        unsigned c2 = (v == gm) ? ii : 0x7fffffffu;
        unsigned gi = redux_min_u32(c2);

        cx = __ldg(X + gi); cy = __ldg(Y + gi); cz = __ldg(Z + gi);
        if (tid == 0 && s + 1 < M) {
            ox[s + 1] = cx; oy[s + 1] = cy; oz[s + 1] = cz;
        }
    }
}

// ---------------------------------------------------------------------------
// Kernel 2: ball query. One warp per center. Scans points in ascending index
// order, ballot-compacts hits, stops after K hits (== sorted-keys-take-k).
// Pads with the first hit index (0 if none), matching the reference.
// ---------------------------------------------------------------------------
__global__ __launch_bounds__(256) void bq_kernel(
    const float* __restrict__ coords, const float* __restrict__ centers)
{
    const int gw   = (blockIdx.x * blockDim.x + threadIdx.x) >> 5;
    const int lane = threadIdx.x & 31;
    if (gw >= BATCH * M) return;
    const int b = gw >> 11, m = gw & (M - 1);

    const float* X = coords + (size_t)b * 3 * NPTS;
    const float* Y = X + NPTS;
    const float* Z = X + 2 * NPTS;
    const float* C = centers + (size_t)b * 3 * M;
    const float cx = C[m], cy = C[M + m], cz = C[2 * M + m];

    const int base = gw * KNN;
    int cnt = 0, firstn = 0;

    for (int c0 = 0; c0 < NPTS; c0 += 32) {
        const int n = c0 + lane;
        float dx = X[n] - cx, dy = Y[n] - cy, dz = Z[n] - cz;
        float d2 = fmaf(dz, dz, fmaf(dy, dy, dx * dx));
        bool hit = d2 < R2;
        unsigned mask = __ballot_sync(0xffffffffu, hit);
        if (cnt == 0 && mask) firstn = c0 + __ffs(mask) - 1;
        int pos = cnt + __popc(mask & ((1u << lane) - 1u));
        if (hit && pos < KNN) g_idx[base + pos] = n;
        cnt += __popc(mask);
        if (cnt >= KNN) break;
    }
    for (int j = cnt + lane; j < KNN; j += 32) g_idx[base + j] = firstn;
}

// ---------------------------------------------------------------------------
// Kernel 2.5: one-time weight transpose into global scratch laid out exactly
// like the mlp kernel's smem image (so mlp blocks do a coalesced flat copy).
//   [0)         w1t [35][64]   w1t[c*64+o]  = W1[o*35+c]
//   [2240)      w2t [64][64]   w2t[c*64+o]  = W2[o*64+c]
//   [6336)      w3t [64][128]  w3t[c*128+o] = W3[o*64+c]
//   [14528)     b1[64]  [14592) b2[64]  [14656) b3[128]
// ---------------------------------------------------------------------------
__global__ void prep_kernel(
    const float* __restrict__ W1, const float* __restrict__ B1,
    const float* __restrict__ W2, const float* __restrict__ B2,
    const float* __restrict__ W3, const float* __restrict__ B3)
{
    int i = blockIdx.x * blockDim.x + threadIdx.x;
    if (i >= WTOT) return;
    float v;
    if (i < 2240)       { int j = i;         int c = j >> 6, o = j & 63;  v = W1[o * 35 + c]; }
    else if (i < 6336)  { int j = i - 2240;  int c = j >> 6, o = j & 63;  v = W2[o * 64 + c]; }
    else if (i < 14528) { int j = i - 6336;  int c = j >> 7, o = j & 127; v = W3[o * 64 + c]; }
    else if (i < 14592) v = B1[i - 14528];
    else if (i < 14656) v = B2[i - 14592];
    else                v = B3[i - 14656];
    g_w[i] = v;
}

// ---------------------------------------------------------------------------
// Kernel 3: gather + 3-layer MLP + max-pool. Warp = center, lane = neighbor.
// Weights pre-transposed in global; block copies them coalesced into smem.
// 1 LDS.128 (broadcast) + 4 FFMA per k-step. Maxpool over k=32 == warp
// butterfly per output channel.
// ---------------------------------------------------------------------------
__global__ __launch_bounds__(256, 1) void mlp_kernel(
    const float* __restrict__ coords, const float* __restrict__ feats,
    const float* __restrict__ centers, float* __restrict__ out)
{
    extern __shared__ float sm[];
    float* w1t = sm;
    float* w2t = w1t + 35 * 64;
    float* w3t = w2t + 64 * 64;
    float* sb1 = w3t + 64 * 128;
    float* sb2 = sb1 + 64;
    float* sb3 = sb2 + 64;

    const int tid = threadIdx.x;
    // coalesced float4 copy of the prebuilt smem image (WTOT = 14784 = 3696*4)
    for (int i = tid; i < WTOT / 4; i += 256)
        ((float4*)sm)[i] = ((const float4*)g_w)[i];
    __syncthreads();

    const int wid = tid >> 5, lane = tid & 31;
    const int gw = blockIdx.x * 8 + wid;
    const int b = gw >> 11, m = gw & (M - 1);

    const int idx = g_idx[gw * KNN + lane];
    const float* X = coords + (size_t)b * 3 * NPTS;
    const float* F = feats + (size_t)b * CF * NPTS;
    const float* C = centers + (size_t)b * 3 * M;

    float in[35];
    in[0] = X[idx]            - C[m];
    in[1] = X[NPTS + idx]     - C[M + m];
    in[2] = X[2 * NPTS + idx] - C[2 * M + m];
#pragma unroll
    for (int c = 0; c < CF; c++) in[3 + c] = F[c * NPTS + idx];

    float h1[64];
#pragma unroll
    for (int og = 0; og < 64; og += 4) {
        float a0 = sb1[og], a1 = sb1[og + 1], a2 = sb1[og + 2], a3 = sb1[og + 3];
#pragma unroll
        for (int c = 0; c < 35; c++) {
            const float4 w = *(const float4*)(w1t + c * 64 + og);
            const float x = in[c];
            a0 = fmaf(w.x, x, a0); a1 = fmaf(w.y, x, a1);
            a2 = fmaf(w.z, x, a2); a3 = fmaf(w.w, x, a3);
        }
        h1[og] = fmaxf(a0, 0.f); h1[og + 1] = fmaxf(a1, 0.f);
        h1[og + 2] = fmaxf(a2, 0.f); h1[og + 3] = fmaxf(a3, 0.f);
    }

    float h2[64];
#pragma unroll
    for (int og = 0; og < 64; og += 4) {
        float a0 = sb2[og], a1 = sb2[og + 1], a2 = sb2[og + 2], a3 = sb2[og + 3];
#pragma unroll
        for (int c = 0; c < 64; c++) {
            const float4 w = *(const float4*)(w2t + c * 64 + og);
            const float x = h1[c];
            a0 = fmaf(w.x, x, a0); a1 = fmaf(w.y, x, a1);
            a2 = fmaf(w.z, x, a2); a3 = fmaf(w.w, x, a3);
        }
        h2[og] = fmaxf(a0, 0.f); h2[og + 1] = fmaxf(a1, 0.f);
        h2[og + 2] = fmaxf(a2, 0.f); h2[og + 3] = fmaxf(a3, 0.f);
    }

    float* O = out + (size_t)b * 128 * M + m;
#pragma unroll
    for (int og = 0; og < 128; og += 4) {
        float a0 = sb3[og], a1 = sb3[og + 1], a2 = sb3[og + 2], a3 = sb3[og + 3];
#pragma unroll
        for (int c = 0; c < 64; c++) {
            const float4 w = *(const float4*)(w3t + c * 128 + og);
            const float x = h2[c];
            a0 = fmaf(w.x, x, a0); a1 = fmaf(w.y, x, a1);
            a2 = fmaf(w.z, x, a2); a3 = fmaf(w.w, x, a3);
        }
        a0 = fmaxf(a0, 0.f); a1 = fmaxf(a1, 0.f);
        a2 = fmaxf(a2, 0.f); a3 = fmaxf(a3, 0.f);
#pragma unroll
        for (int off = 16; off; off >>= 1) {
            a0 = fmaxf(a0, __shfl_xor_sync(0xffffffffu, a0, off));
            a1 = fmaxf(a1, __shfl_xor_sync(0xffffffffu, a1, off));
            a2 = fmaxf(a2, __shfl_xor_sync(0xffffffffu, a2, off));
            a3 = fmaxf(a3, __shfl_xor_sync(0xffffffffu, a3, off));
        }
        if (lane == 0) {
            O[(og + 0) * M] = a0; O[(og + 1) * M] = a1;
            O[(og + 2) * M] = a2; O[(og + 3) * M] = a3;
        }
    }
}

// ---------------------------------------------------------------------------
extern "C" void kernel_launch(void* const* d_in, const int* in_sizes, int n_in,
                              void* d_out, int out_size)
{
    const float* feats  = (const float*)d_in[0];
    const float* coords = (const float*)d_in[1];
    const float* W1 = (const float*)d_in[2];
    const float* B1 = (const float*)d_in[3];
    const float* W2 = (const float*)d_in[4];
    const float* B2 = (const float*)d_in[5];
    const float* W3 = (const float*)d_in[6];
    const float* B3 = (const float*)d_in[7];

    float* out     = (float*)d_out;
    float* centers = out + (size_t)BATCH * 128 * M;

    fps_kernel<<<BATCH, 1024>>>(coords, centers);

    prep_kernel<<<(WTOT + 255) / 256, 256>>>(W1, B1, W2, B2, W3, B3);

    bq_kernel<<<(BATCH * M) / 8, 256>>>(coords, centers);

    const int SMEM = WTOT * 4;
    cudaFuncSetAttribute(mlp_kernel, cudaFuncAttributeMaxDynamicSharedMemorySize, SMEM);
    mlp_kernel<<<(BATCH * M) / 8, 256, SMEM>>>(coords, feats, centers, out);
}

// round 4
// speedup vs baseline: 1.5773x; 1.1968x over previous
#include <cuda_runtime.h>

#define NPTS   8192
#define BATCH  4
#define M      2048
#define KNN    32
#define CF     32
#define R2     0.04f

typedef unsigned long long ull;

// scratch (no allocations allowed)
__device__ int   g_idx[BATCH * M * KNN];
#define WTOT (35*64 + 64*64 + 64*128 + 64 + 64 + 128)   // 14784
__device__ float g_w[WTOT];
// h1 staging: [gw (8192)][channel-pair (32)][neighbor lane (32)], packed f32x2
__device__ ull   g_h1[(size_t)BATCH * M * 32 * 32];

// ---- packed f32x2 helpers (bit-identical IEEE f32 per lane) ----------------
__device__ __forceinline__ ull f2pack(float a, float b) {
    ull r; asm("mov.b64 %0, {%1,%2};" : "=l"(r) : "f"(a), "f"(b)); return r;
}
__device__ __forceinline__ void f2unpack(ull v, float& a, float& b) {
    asm("mov.b64 {%0,%1}, %2;" : "=f"(a), "=f"(b) : "l"(v));
}
#define F2ADD(d, a, b)    asm("add.rn.f32x2 %0, %1, %2;"     : "=l"(d) : "l"(a), "l"(b))
#define F2MUL(d, a, b)    asm("mul.rn.f32x2 %0, %1, %2;"     : "=l"(d) : "l"(a), "l"(b))
#define F2FMA(d, a, b, c) asm("fma.rn.f32x2 %0, %1, %2, %3;" : "=l"(d) : "l"(a), "l"(b), "l"(c))

__device__ __forceinline__ unsigned redux_max_u32(unsigned v) {
    unsigned r; asm("redux.sync.max.u32 %0, %1, 0xffffffff;" : "=r"(r) : "r"(v)); return r;
}
__device__ __forceinline__ unsigned redux_min_u32(unsigned v) {
    unsigned r; asm("redux.sync.min.u32 %0, %1, 0xffffffff;" : "=r"(r) : "r"(v)); return r;
}

// ---------------------------------------------------------------------------
// Kernel 1: furthest point sampling. One block per batch, 512 threads,
// 16 points per thread (8 f32x2 pairs) in registers. One barrier per
// iteration; every warp redundantly reduces the 16 warp keys (redux.max on
// distance bits + redux.min on masked index = exact lowest-index tie-break)
// and loads the next centroid itself (lane-invariant L1 broadcast LDG).
// ---------------------------------------------------------------------------
__global__ __launch_bounds__(512, 1) void fps_kernel(
    const float* __restrict__ coords, float* __restrict__ centers)
{
    const int b = blockIdx.x, tid = threadIdx.x;
    const int wid = tid >> 5, lane = tid & 31;
    const float* X = coords + (size_t)b * 3 * NPTS;
    const float* Y = X + NPTS;
    const float* Z = X + 2 * NPTS;

    ull px2[8], py2[8], pz2[8];
    float dl[16];
#pragma unroll
    for (int j = 0; j < 8; j++) {
        int n0 = tid + (2 * j) * 512, n1 = tid + (2 * j + 1) * 512;
        px2[j] = f2pack(X[n0], X[n1]);
        py2[j] = f2pack(Y[n0], Y[n1]);
        pz2[j] = f2pack(Z[n0], Z[n1]);
        dl[2 * j] = 1e30f; dl[2 * j + 1] = 1e30f;
    }

    __shared__ ull skey[2][16];

    float* ox = centers + (size_t)b * 3 * M;
    float* oy = ox + M;
    float* oz = ox + 2 * M;

    float cx = __ldg(X), cy = __ldg(Y), cz = __ldg(Z);
    if (tid == 0) { ox[0] = cx; oy[0] = cy; oz[0] = cz; }

    for (int s = 0; s < M; s++) {
        const ull ncx = f2pack(-cx, -cx);
        const ull ncy = f2pack(-cy, -cy);
        const ull ncz = f2pack(-cz, -cz);

        float bm = -1.0f;
        int bp = 0;
#pragma unroll
        for (int j = 0; j < 8; j++) {
            ull dx, dy, dz, t;
            F2ADD(dx, px2[j], ncx);
            F2ADD(dy, py2[j], ncy);
            F2ADD(dz, pz2[j], ncz);
            F2MUL(t, dx, dx);
            F2FMA(t, dy, dy, t);
            F2FMA(t, dz, dz, t);
            float t0, t1; f2unpack(t, t0, t1);
            float d0 = fminf(dl[2 * j],     t0); dl[2 * j]     = d0;
            float d1 = fminf(dl[2 * j + 1], t1); dl[2 * j + 1] = d1;
            float m = fmaxf(d0, d1);
            if (m > bm) { bm = m; bp = j; }   // strict >: lowest pair wins
        }
        // lowest-index disambiguation inside the winning pair (exact)
        int bi = (dl[2 * bp] == bm) ? (tid + (2 * bp) * 512)
                                    : (tid + (2 * bp + 1) * 512);

        unsigned mb = __float_as_uint(bm);          // bm >= 0 -> monotone bits
        unsigned wm = redux_max_u32(mb);
        unsigned ci = (mb == wm) ? (unsigned)bi : 0x7fffffffu;
        unsigned wi = redux_min_u32(ci);
        if (lane == 0) skey[s & 1][wid] = ((ull)wm << 32) | wi;
        __syncthreads();

        // stage 2: every warp reduces the 16 warp keys (lanes 16-31 duplicate)
        ull k = skey[s & 1][lane & 15];
        unsigned v  = (unsigned)(k >> 32);
        unsigned ii = (unsigned)k;
        unsigned gm = redux_max_u32(v);
        unsigned c2 = (v == gm) ? ii : 0x7fffffffu;
        unsigned gi = redux_min_u32(c2);

        cx = __ldg(X + gi); cy = __ldg(Y + gi); cz = __ldg(Z + gi);
        if (tid == 0 && s + 1 < M) {
            ox[s + 1] = cx; oy[s + 1] = cy; oz[s + 1] = cz;
        }
    }
}

// ---------------------------------------------------------------------------
// Kernel 2: ball query (unchanged; ~30us).
// ---------------------------------------------------------------------------
__global__ __launch_bounds__(256) void bq_kernel(
    const float* __restrict__ coords, const float* __restrict__ centers)
{
    const int gw   = (blockIdx.x * blockDim.x + threadIdx.x) >> 5;
    const int lane = threadIdx.x & 31;
    if (gw >= BATCH * M) return;
    const int b = gw >> 11, m = gw & (M - 1);

    const float* X = coords + (size_t)b * 3 * NPTS;
    const float* Y = X + NPTS;
    const float* Z = X + 2 * NPTS;
    const float* C = centers + (size_t)b * 3 * M;
    const float cx = C[m], cy = C[M + m], cz = C[2 * M + m];

    const int base = gw * KNN;
    int cnt = 0, firstn = 0;

    for (int c0 = 0; c0 < NPTS; c0 += 32) {
        const int n = c0 + lane;
        float dx = X[n] - cx, dy = Y[n] - cy, dz = Z[n] - cz;
        float d2 = fmaf(dz, dz, fmaf(dy, dy, dx * dx));
        bool hit = d2 < R2;
        unsigned mask = __ballot_sync(0xffffffffu, hit);
        if (cnt == 0 && mask) firstn = c0 + __ffs(mask) - 1;
        int pos = cnt + __popc(mask & ((1u << lane) - 1u));
        if (hit && pos < KNN) g_idx[base + pos] = n;
        cnt += __popc(mask);
        if (cnt >= KNN) break;
    }
    for (int j = cnt + lane; j < KNN; j += 32) g_idx[base + j] = firstn;
}

// ---------------------------------------------------------------------------
// Kernel 2.5: one-time weight transpose into global scratch, laid out as the
// mlp kernels' smem images.
//   [0)      w1t [35][64]   [2240)  w2t [64][64]   [6336)  w3t [64][128]
//   [14528)  b1[64]         [14592) b2[64]         [14656) b3[128]
// ---------------------------------------------------------------------------
__global__ void prep_kernel(
    const float* __restrict__ W1, const float* __restrict__ B1,
    const float* __restrict__ W2, const float* __restrict__ B2,
    const float* __restrict__ W3, const float* __restrict__ B3)
{
    int i = blockIdx.x * blockDim.x + threadIdx.x;
    if (i >= WTOT) return;
    float v;
    if (i < 2240)       { int j = i;         int c = j >> 6, o = j & 63;  v = W1[o * 35 + c]; }
    else if (i < 6336)  { int j = i - 2240;  int c = j >> 6, o = j & 63;  v = W2[o * 64 + c]; }
    else if (i < 14528) { int j = i - 6336;  int c = j >> 7, o = j & 127; v = W3[o * 64 + c]; }
    else if (i < 14592) v = B1[i - 14528];
    else if (i < 14656) v = B2[i - 14592];
    else                v = B3[i - 14656];
    g_w[i] = v;
}

// ---------------------------------------------------------------------------
// Kernel 3a: gather + layer1 (35->64) with packed f32x2 accumulators.
// Warp = center, lane = neighbor. Writes relu(h1) packed as f32x2 pairs to
// g_h1 laid out [center][ch-pair][lane] so both store and reload coalesce.
// ---------------------------------------------------------------------------
__global__ __launch_bounds__(256, 2) void mlp1_kernel(
    const float* __restrict__ coords, const float* __restrict__ feats,
    const float* __restrict__ centers)
{
    extern __shared__ float sm[];           // w1t (2240) + b1 (64)
    const int tid = threadIdx.x;
    for (int i = tid; i < 560; i += 256)
        ((float4*)sm)[i] = ((const float4*)g_w)[i];
    if (tid < 64) sm[2240 + tid] = g_w[14528 + tid];
    __syncthreads();

    const int wid = tid >> 5, lane = tid & 31;
    const int gw = blockIdx.x * 8 + wid;
    const int b = gw >> 11, m = gw & (M - 1);

    const int idx = g_idx[gw * KNN + lane];
    const float* X = coords + (size_t)b * 3 * NPTS;
    const float* F = feats + (size_t)b * CF * NPTS;
    const float* C = centers + (size_t)b * 3 * M;

    float in[35];
    in[0] = X[idx]            - C[m];
    in[1] = X[NPTS + idx]     - C[M + m];
    in[2] = X[2 * NPTS + idx] - C[2 * M + m];
#pragma unroll
    for (int c = 0; c < CF; c++) in[3 + c] = F[c * NPTS + idx];

    ull acc[32];
    const ull* bp = (const ull*)(sm + 2240);
#pragma unroll
    for (int i = 0; i < 32; i++) acc[i] = bp[i];

#pragma unroll
    for (int c = 0; c < 35; c++) {
        const ull xx = f2pack(in[c], in[c]);
        const ulonglong2* pw = (const ulonglong2*)(sm + c * 64);
#pragma unroll
        for (int i = 0; i < 16; i++) {
            const ulonglong2 w = pw[i];
            F2FMA(acc[2 * i],     w.x, xx, acc[2 * i]);
            F2FMA(acc[2 * i + 1], w.y, xx, acc[2 * i + 1]);
        }
    }

    ull* H = g_h1 + (size_t)gw * 1024 + lane;
#pragma unroll
    for (int i = 0; i < 32; i++) {
        float a, c2; f2unpack(acc[i], a, c2);
        H[i * 32] = f2pack(fmaxf(a, 0.f), fmaxf(c2, 0.f));
    }
}

// ---------------------------------------------------------------------------
// Kernel 3b: layer2 (64->64) + layer3 (64->128) + maxpool, packed f32x2.
// Streams h1 from g_h1 (coalesced, L2-resident). Layer3 processed in 4
// chunks of 32 outputs (q-loop rolled) to bound registers and code size.
// ---------------------------------------------------------------------------
__global__ __launch_bounds__(256, 2) void mlp2_kernel(float* __restrict__ out)
{
    extern __shared__ float sm[];   // g_w[2240..14784): w2t@0, w3t@4096, b2@12352-2240.. 
    const int tid = threadIdx.x;
    for (int i = tid; i < 3136; i += 256)
        ((float4*)sm)[i] = ((const float4*)(g_w + 2240))[i];
    __syncthreads();

    float* w2t = sm;                 // [64][64]
    float* w3t = sm + 4096;          // [64][128]
    const ull* bias2 = (const ull*)(sm + 12352);  // b2 (g_w 14592)
    const ull* bias3 = (const ull*)(sm + 12416);  // b3 (g_w 14656)

    const int wid = tid >> 5, lane = tid & 31;
    const int gw = blockIdx.x * 8 + wid;
    const int b = gw >> 11, m = gw & (M - 1);

    const ull* H = g_h1 + (size_t)gw * 1024 + lane;

    // ---- layer 2: h2 = relu(W2 . h1 + b2), 32 packed accumulators ----
    ull acc[32];
#pragma unroll
    for (int i = 0; i < 32; i++) acc[i] = bias2[i];

    for (int blk = 0; blk < 4; blk++) {
        ull h1p[8];
#pragma unroll
        for (int t = 0; t < 8; t++) h1p[t] = H[(blk * 8 + t) * 32];
#pragma unroll
        for (int t = 0; t < 8; t++) {
            float x0, x1; f2unpack(h1p[t], x0, x1);
            const ull xx0 = f2pack(x0, x0), xx1 = f2pack(x1, x1);
            const int c = blk * 16 + 2 * t;
            const ulonglong2* pw0 = (const ulonglong2*)(w2t + c * 64);
            const ulonglong2* pw1 = (const ulonglong2*)(w2t + (c + 1) * 64);
#pragma unroll
            for (int i = 0; i < 16; i++) {
                const ulonglong2 w = pw0[i];
                F2FMA(acc[2 * i],     w.x, xx0, acc[2 * i]);
                F2FMA(acc[2 * i + 1], w.y, xx0, acc[2 * i + 1]);
            }
#pragma unroll
            for (int i = 0; i < 16; i++) {
                const ulonglong2 w = pw1[i];
                F2FMA(acc[2 * i],     w.x, xx1, acc[2 * i]);
                F2FMA(acc[2 * i + 1], w.y, xx1, acc[2 * i + 1]);
            }
        }
    }

    float h2[64];
#pragma unroll
    for (int i = 0; i < 32; i++) {
        float a, c2; f2unpack(acc[i], a, c2);
        h2[2 * i] = fmaxf(a, 0.f); h2[2 * i + 1] = fmaxf(c2, 0.f);
    }

    // ---- layer 3 + relu + warp maxpool, 4 chunks of 32 outputs ----
    float* O = out + (size_t)b * 128 * M + m;
    for (int q = 0; q < 4; q++) {
        ull a3[16];
#pragma unroll
        for (int i = 0; i < 16; i++) a3[i] = bias3[q * 16 + i];
#pragma unroll
        for (int c = 0; c < 64; c++) {
            const ull xx = f2pack(h2[c], h2[c]);
            const ulonglong2* pw = (const ulonglong2*)(w3t + c * 128 + q * 32);
#pragma unroll
            for (int i = 0; i < 8; i++) {
                const ulonglong2 w = pw[i];
                F2FMA(a3[2 * i],     w.x, xx, a3[2 * i]);
                F2FMA(a3[2 * i + 1], w.y, xx, a3[2 * i + 1]);
            }
        }
#pragma unroll
        for (int i = 0; i < 16; i++) {
            float u, v; f2unpack(a3[i], u, v);
            u = fmaxf(u, 0.f); v = fmaxf(v, 0.f);
#pragma unroll
            for (int off = 16; off; off >>= 1) {
                u = fmaxf(u, __shfl_xor_sync(0xffffffffu, u, off));
                v = fmaxf(v, __shfl_xor_sync(0xffffffffu, v, off));
            }
            if (lane == 0) {
                O[(q * 32 + 2 * i) * M]     = u;
                O[(q * 32 + 2 * i + 1) * M] = v;
            }
        }
    }
}

// ---------------------------------------------------------------------------
extern "C" void kernel_launch(void* const* d_in, const int* in_sizes, int n_in,
                              void* d_out, int out_size)
{
    const float* feats  = (const float*)d_in[0];
    const float* coords = (const float*)d_in[1];
    const float* W1 = (const float*)d_in[2];
    const float* B1 = (const float*)d_in[3];
    const float* W2 = (const float*)d_in[4];
    const float* B2 = (const float*)d_in[5];
    const float* W3 = (const float*)d_in[6];
    const float* B3 = (const float*)d_in[7];

    float* out     = (float*)d_out;
    float* centers = out + (size_t)BATCH * 128 * M;

    fps_kernel<<<BATCH, 512>>>(coords, centers);

    prep_kernel<<<(WTOT + 255) / 256, 256>>>(W1, B1, W2, B2, W3, B3);

    bq_kernel<<<(BATCH * M) / 8, 256>>>(coords, centers);

    const int SMEM1 = 2304 * 4;
    const int SMEM2 = 12544 * 4;
    cudaFuncSetAttribute(mlp1_kernel, cudaFuncAttributeMaxDynamicSharedMemorySize, SMEM1);
    cudaFuncSetAttribute(mlp2_kernel, cudaFuncAttributeMaxDynamicSharedMemorySize, SMEM2);
    mlp1_kernel<<<(BATCH * M) / 8, 256, SMEM1>>>(coords, feats, centers);
    mlp2_kernel<<<(BATCH * M) / 8, 256, SMEM2>>>(out);
}

// round 5
// speedup vs baseline: 1.7652x; 1.1191x over previous
#include <cuda_runtime.h>

#define NPTS   8192
#define BATCH  4
#define M      2048
#define KNN    32
#define CF     32
#define R2     0.04f

typedef unsigned long long ull;

// scratch (no allocations allowed)
__device__ int   g_idx[BATCH * M * KNN];
#define WTOT (35*64 + 64*64 + 64*128 + 64 + 64 + 128)   // 14784
__device__ float g_w[WTOT];
// h1 staging: [gw (8192)][channel-pair (32)][neighbor lane (32)], packed f32x2
__device__ ull   g_h1[(size_t)BATCH * M * 32 * 32];
// spatially sorted points (Morton-cell order) + original indices
__device__ float g_sx[BATCH * NPTS], g_sy[BATCH * NPTS], g_sz[BATCH * NPTS];
__device__ int   g_si[BATCH * NPTS];

// ---- packed f32x2 helpers (bit-identical IEEE f32 per lane) ----------------
__device__ __forceinline__ ull f2pack(float a, float b) {
    ull r; asm("mov.b64 %0, {%1,%2};" : "=l"(r) : "f"(a), "f"(b)); return r;
}
__device__ __forceinline__ void f2unpack(ull v, float& a, float& b) {
    asm("mov.b64 {%0,%1}, %2;" : "=f"(a), "=f"(b) : "l"(v));
}
#define F2ADD(d, a, b)    asm("add.rn.f32x2 %0, %1, %2;"     : "=l"(d) : "l"(a), "l"(b))
#define F2MUL(d, a, b)    asm("mul.rn.f32x2 %0, %1, %2;"     : "=l"(d) : "l"(a), "l"(b))
#define F2FMA(d, a, b, c) asm("fma.rn.f32x2 %0, %1, %2, %3;" : "=l"(d) : "l"(a), "l"(b), "l"(c))

__device__ __forceinline__ unsigned redux_max_u32(unsigned v) {
    unsigned r; asm("redux.sync.max.u32 %0, %1, 0xffffffff;" : "=r"(r) : "r"(v)); return r;
}
__device__ __forceinline__ unsigned redux_min_u32(unsigned v) {
    unsigned r; asm("redux.sync.min.u32 %0, %1, 0xffffffff;" : "=r"(r) : "r"(v)); return r;
}

__device__ __forceinline__ unsigned spread3_4(unsigned v) {  // 4 bits -> every 3rd
    unsigned r = (v & 1u);
    r |= (v & 2u) << 2;
    r |= (v & 4u) << 4;
    r |= (v & 8u) << 6;
    return r;
}

// ---------------------------------------------------------------------------
// Kernel 0: spatial bucket sort. One block per batch. 16^3 grid, cells
// enumerated in Morton order so consecutive sorted points are spatially
// coherent. Counting sort: smem histogram -> block scan -> atomic scatter.
// (Intra-cell order is nondeterministic; final outputs are invariant to it.)
// ---------------------------------------------------------------------------
__global__ __launch_bounds__(1024, 1) void sort_kernel(const float* __restrict__ coords)
{
    __shared__ int cnt[4096];
    __shared__ int ss[1024];
    const int b = blockIdx.x, tid = threadIdx.x;
    const float* X = coords + (size_t)b * 3 * NPTS;
    const float* Y = X + NPTS;
    const float* Z = X + 2 * NPTS;

    for (int i = tid; i < 4096; i += 1024) cnt[i] = 0;
    __syncthreads();

    int cell8[8];
#pragma unroll
    for (int i = 0; i < 8; i++) {
        int n = tid + i * 1024;
        int cx = min(15, (int)(X[n] * 16.0f));
        int cy = min(15, (int)(Y[n] * 16.0f));
        int cz = min(15, (int)(Z[n] * 16.0f));
        int cell = spread3_4(cx) | (spread3_4(cy) << 1) | (spread3_4(cz) << 2);
        cell8[i] = cell;
        atomicAdd(&cnt[cell], 1);
    }
    __syncthreads();

    // block exclusive scan over 4096 counts (each thread owns 4)
    int l0 = cnt[4 * tid], l1 = cnt[4 * tid + 1], l2 = cnt[4 * tid + 2], l3 = cnt[4 * tid + 3];
    int local = l0 + l1 + l2 + l3;
    ss[tid] = local;
    __syncthreads();
    for (int off = 1; off < 1024; off <<= 1) {
        int v = (tid >= off) ? ss[tid - off] : 0;
        __syncthreads();
        ss[tid] += v;
        __syncthreads();
    }
    int ex = ss[tid] - local;
    cnt[4 * tid]     = ex;
    cnt[4 * tid + 1] = ex + l0;
    cnt[4 * tid + 2] = ex + l0 + l1;
    cnt[4 * tid + 3] = ex + l0 + l1 + l2;
    __syncthreads();

#pragma unroll
    for (int i = 0; i < 8; i++) {
        int n = tid + i * 1024;
        int pos = atomicAdd(&cnt[cell8[i]], 1);
        g_sx[b * NPTS + pos] = X[n];
        g_sy[b * NPTS + pos] = Y[n];
        g_sz[b * NPTS + pos] = Z[n];
        g_si[b * NPTS + pos] = n;
    }
}

// ---------------------------------------------------------------------------
// Kernel 1: furthest point sampling with exact spatial pruning.
// One block per batch, 512 threads, 16 spatially-contiguous points/thread.
// Per iteration each thread computes a conservative lower bound on the
// distance from the new centroid to its bbox; if lb2*0.999 > dl_max the
// update provably leaves every owned dl unchanged (min(dl,d)=dl bit-exact),
// so the thread reuses its cached best key. Ties broken on ORIGINAL index
// (explicit compares in-thread, redux.min across threads) == jnp.argmax.
// ---------------------------------------------------------------------------
__global__ __launch_bounds__(512, 1) void fps_kernel(
    const float* __restrict__ coords, float* __restrict__ centers)
{
    const int b = blockIdx.x, tid = threadIdx.x;
    const int wid = tid >> 5, lane = tid & 31;
    const float* X = coords + (size_t)b * 3 * NPTS;
    const float* Y = X + NPTS;
    const float* Z = X + 2 * NPTS;
    const float* SX = g_sx + b * NPTS;
    const float* SY = g_sy + b * NPTS;
    const float* SZ = g_sz + b * NPTS;
    const int*   SI = g_si + b * NPTS;

    ull px2[8], py2[8], pz2[8];
    int oi[16];
    float dl[16];
    float bxmin = 1e30f, bxmax = -1e30f, bymin = 1e30f, bymax = -1e30f,
          bzmin = 1e30f, bzmax = -1e30f;
    const int base = tid * 16;
#pragma unroll
    for (int j = 0; j < 8; j++) {
        float x0 = SX[base + 2*j], x1 = SX[base + 2*j + 1];
        float y0 = SY[base + 2*j], y1 = SY[base + 2*j + 1];
        float z0 = SZ[base + 2*j], z1 = SZ[base + 2*j + 1];
        px2[j] = f2pack(x0, x1); py2[j] = f2pack(y0, y1); pz2[j] = f2pack(z0, z1);
        oi[2*j] = SI[base + 2*j]; oi[2*j + 1] = SI[base + 2*j + 1];
        dl[2*j] = 1e30f; dl[2*j + 1] = 1e30f;
        bxmin = fminf(bxmin, fminf(x0, x1)); bxmax = fmaxf(bxmax, fmaxf(x0, x1));
        bymin = fminf(bymin, fminf(y0, y1)); bymax = fmaxf(bymax, fmaxf(y0, y1));
        bzmin = fminf(bzmin, fminf(z0, z1)); bzmax = fmaxf(bzmax, fmaxf(z0, z1));
    }

    __shared__ ull skey[2][16];

    float* ox = centers + (size_t)b * 3 * M;
    float* oy = ox + M;
    float* oz = ox + 2 * M;

    float cx = __ldg(X), cy = __ldg(Y), cz = __ldg(Z);
    if (tid == 0) { ox[0] = cx; oy[0] = cy; oz[0] = cz; }

    float bm = 1e30f;            // cached thread-best distance (== max of dl)
    int   bi = 0x7fffffff;       // cached thread-best original index

    for (int s = 0; s < M; s++) {
        // conservative lower bound on d2(c, any owned point)
        float tx = fmaxf(fmaxf(bxmin - cx, cx - bxmax), 0.0f);
        float ty = fmaxf(fmaxf(bymin - cy, cy - bymax), 0.0f);
        float tz = fmaxf(fmaxf(bzmin - cz, cz - bzmax), 0.0f);
        float lb2 = fmaf(tz, tz, fmaf(ty, ty, tx * tx));

        if (!(lb2 * 0.999f > bm)) {          // active: some dl may change
            const ull ncx = f2pack(-cx, -cx);
            const ull ncy = f2pack(-cy, -cy);
            const ull ncz = f2pack(-cz, -cz);
            float nbm = -1.0f; int nbi = 0x7fffffff;
#pragma unroll
            for (int j = 0; j < 8; j++) {
                ull dx, dy, dz, t;
                F2ADD(dx, px2[j], ncx);
                F2ADD(dy, py2[j], ncy);
                F2ADD(dz, pz2[j], ncz);
                F2MUL(t, dx, dx);
                F2FMA(t, dy, dy, t);
                F2FMA(t, dz, dz, t);
                float t0, t1; f2unpack(t, t0, t1);
                float d0 = fminf(dl[2*j],     t0); dl[2*j]     = d0;
                float d1 = fminf(dl[2*j + 1], t1); dl[2*j + 1] = d1;
                const int i0 = oi[2*j], i1 = oi[2*j + 1];
                float m; int mi;
                if (d0 > d1 || (d0 == d1 && i0 < i1)) { m = d0; mi = i0; }
                else                                  { m = d1; mi = i1; }
                if (m > nbm || (m == nbm && mi < nbi)) { nbm = m; nbi = mi; }
            }
            bm = nbm; bi = nbi;
        }

        // warp reduce: max distance bits, then min original index among ties
        unsigned mb = __float_as_uint(bm);          // bm >= 0 -> monotone bits
        unsigned wm = redux_max_u32(mb);
        unsigned ci = (mb == wm) ? (unsigned)bi : 0x7fffffffu;
        unsigned wi = redux_min_u32(ci);
        if (lane == 0) skey[s & 1][wid] = ((ull)wm << 32) | wi;
        __syncthreads();

        // stage 2: every warp reduces the 16 warp keys redundantly
        ull k = skey[s & 1][lane & 15];
        unsigned v  = (unsigned)(k >> 32);
        unsigned ii = (unsigned)k;
        unsigned gm = redux_max_u32(v);
        unsigned c2 = (v == gm) ? ii : 0x7fffffffu;
        unsigned gi = redux_min_u32(c2);

        cx = __ldg(X + gi); cy = __ldg(Y + gi); cz = __ldg(Z + gi);
        if (tid == 0 && s + 1 < M) {
            ox[s + 1] = cx; oy[s + 1] = cy; oz[s + 1] = cz;
        }
    }
}

// ---------------------------------------------------------------------------
// Kernel 2: ball query. One warp per center; ascending-index scan with
// ballot compaction, early-exit at K hits; pads with first hit (0 if none).
// ---------------------------------------------------------------------------
__global__ __launch_bounds__(256) void bq_kernel(
    const float* __restrict__ coords, const float* __restrict__ centers)
{
    const int gw   = (blockIdx.x * blockDim.x + threadIdx.x) >> 5;
    const int lane = threadIdx.x & 31;
    if (gw >= BATCH * M) return;
    const int b = gw >> 11, m = gw & (M - 1);

    const float* X = coords + (size_t)b * 3 * NPTS;
    const float* Y = X + NPTS;
    const float* Z = X + 2 * NPTS;
    const float* C = centers + (size_t)b * 3 * M;
    const float cx = C[m], cy = C[M + m], cz = C[2 * M + m];

    const int base = gw * KNN;
    int cnt = 0, firstn = 0;

    for (int c0 = 0; c0 < NPTS; c0 += 32) {
        const int n = c0 + lane;
        float dx = X[n] - cx, dy = Y[n] - cy, dz = Z[n] - cz;
        float d2 = fmaf(dz, dz, fmaf(dy, dy, dx * dx));
        bool hit = d2 < R2;
        unsigned mask = __ballot_sync(0xffffffffu, hit);
        if (cnt == 0 && mask) firstn = c0 + __ffs(mask) - 1;
        int pos = cnt + __popc(mask & ((1u << lane) - 1u));
        if (hit && pos < KNN) g_idx[base + pos] = n;
        cnt += __popc(mask);
        if (cnt >= KNN) break;
    }
    for (int j = cnt + lane; j < KNN; j += 32) g_idx[base + j] = firstn;
}

// ---------------------------------------------------------------------------
// Kernel 2.5: one-time weight transpose into global scratch (smem images).
// ---------------------------------------------------------------------------
__global__ void prep_kernel(
    const float* __restrict__ W1, const float* __restrict__ B1,
    const float* __restrict__ W2, const float* __restrict__ B2,
    const float* __restrict__ W3, const float* __restrict__ B3)
{
    int i = blockIdx.x * blockDim.x + threadIdx.x;
    if (i >= WTOT) return;
    float v;
    if (i < 2240)       { int j = i;         int c = j >> 6, o = j & 63;  v = W1[o * 35 + c]; }
    else if (i < 6336)  { int j = i - 2240;  int c = j >> 6, o = j & 63;  v = W2[o * 64 + c]; }
    else if (i < 14528) { int j = i - 6336;  int c = j >> 7, o = j & 127; v = W3[o * 64 + c]; }
    else if (i < 14592) v = B1[i - 14528];
    else if (i < 14656) v = B2[i - 14592];
    else                v = B3[i - 14656];
    g_w[i] = v;
}

// ---------------------------------------------------------------------------
// Kernel 3a: gather + layer1 (35->64), packed f32x2 accumulators.
// ---------------------------------------------------------------------------
__global__ __launch_bounds__(256, 2) void mlp1_kernel(
    const float* __restrict__ coords, const float* __restrict__ feats,
    const float* __restrict__ centers)
{
    extern __shared__ float sm[];           // w1t (2240) + b1 (64)
    const int tid = threadIdx.x;
    for (int i = tid; i < 560; i += 256)
        ((float4*)sm)[i] = ((const float4*)g_w)[i];
    if (tid < 64) sm[2240 + tid] = g_w[14528 + tid];
    __syncthreads();

    const int wid = tid >> 5, lane = tid & 31;
    const int gw = blockIdx.x * 8 + wid;
    const int b = gw >> 11, m = gw & (M - 1);

    const int idx = g_idx[gw * KNN + lane];
    const float* X = coords + (size_t)b * 3 * NPTS;
    const float* F = feats + (size_t)b * CF * NPTS;
    const float* C = centers + (size_t)b * 3 * M;

    float in[35];
    in[0] = X[idx]            - C[m];
    in[1] = X[NPTS + idx]     - C[M + m];
    in[2] = X[2 * NPTS + idx] - C[2 * M + m];
#pragma unroll
    for (int c = 0; c < CF; c++) in[3 + c] = F[c * NPTS + idx];

    ull acc[32];
    const ull* bp = (const ull*)(sm + 2240);
#pragma unroll
    for (int i = 0; i < 32; i++) acc[i] = bp[i];

#pragma unroll
    for (int c = 0; c < 35; c++) {
        const ull xx = f2pack(in[c], in[c]);
        const ulonglong2* pw = (const ulonglong2*)(sm + c * 64);
#pragma unroll
        for (int i = 0; i < 16; i++) {
            const ulonglong2 w = pw[i];
            F2FMA(acc[2 * i],     w.x, xx, acc[2 * i]);
            F2FMA(acc[2 * i + 1], w.y, xx, acc[2 * i + 1]);
        }
    }

    ull* H = g_h1 + (size_t)gw * 1024 + lane;
#pragma unroll
    for (int i = 0; i < 32; i++) {
        float a, c2; f2unpack(acc[i], a, c2);
        H[i * 32] = f2pack(fmaxf(a, 0.f), fmaxf(c2, 0.f));
    }
}

// ---------------------------------------------------------------------------
// Kernel 3b: layer2 + layer3 + maxpool, packed f32x2.
// ---------------------------------------------------------------------------
__global__ __launch_bounds__(256, 2) void mlp2_kernel(float* __restrict__ out)
{
    extern __shared__ float sm[];
    const int tid = threadIdx.x;
    for (int i = tid; i < 3136; i += 256)
        ((float4*)sm)[i] = ((const float4*)(g_w + 2240))[i];
    __syncthreads();

    float* w2t = sm;                 // [64][64]
    float* w3t = sm + 4096;          // [64][128]
    const ull* bias2 = (const ull*)(sm + 12352);
    const ull* bias3 = (const ull*)(sm + 12416);

    const int wid = tid >> 5, lane = tid & 31;
    const int gw = blockIdx.x * 8 + wid;
    const int b = gw >> 11, m = gw & (M - 1);

    const ull* H = g_h1 + (size_t)gw * 1024 + lane;

    ull acc[32];
#pragma unroll
    for (int i = 0; i < 32; i++) acc[i] = bias2[i];

    for (int blk = 0; blk < 4; blk++) {
        ull h1p[8];
#pragma unroll
        for (int t = 0; t < 8; t++) h1p[t] = H[(blk * 8 + t) * 32];
#pragma unroll
        for (int t = 0; t < 8; t++) {
            float x0, x1; f2unpack(h1p[t], x0, x1);
            const ull xx0 = f2pack(x0, x0), xx1 = f2pack(x1, x1);
            const int c = blk * 16 + 2 * t;
            const ulonglong2* pw0 = (const ulonglong2*)(w2t + c * 64);
            const ulonglong2* pw1 = (const ulonglong2*)(w2t + (c + 1) * 64);
#pragma unroll
            for (int i = 0; i < 16; i++) {
                const ulonglong2 w = pw0[i];
                F2FMA(acc[2 * i],     w.x, xx0, acc[2 * i]);
                F2FMA(acc[2 * i + 1], w.y, xx0, acc[2 * i + 1]);
            }
#pragma unroll
            for (int i = 0; i < 16; i++) {
                const ulonglong2 w = pw1[i];
                F2FMA(acc[2 * i],     w.x, xx1, acc[2 * i]);
                F2FMA(acc[2 * i + 1], w.y, xx1, acc[2 * i + 1]);
            }
        }
    }

    float h2[64];
#pragma unroll
    for (int i = 0; i < 32; i++) {
        float a, c2; f2unpack(acc[i], a, c2);
        h2[2 * i] = fmaxf(a, 0.f); h2[2 * i + 1] = fmaxf(c2, 0.f);
    }

    float* O = out + (size_t)b * 128 * M + m;
    for (int q = 0; q < 4; q++) {
        ull a3[16];
#pragma unroll
        for (int i = 0; i < 16; i++) a3[i] = bias3[q * 16 + i];
#pragma unroll
        for (int c = 0; c < 64; c++) {
            const ull xx = f2pack(h2[c], h2[c]);
            const ulonglong2* pw = (const ulonglong2*)(w3t + c * 128 + q * 32);
#pragma unroll
            for (int i = 0; i < 8; i++) {
                const ulonglong2 w = pw[i];
                F2FMA(a3[2 * i],     w.x, xx, a3[2 * i]);
                F2FMA(a3[2 * i + 1], w.y, xx, a3[2 * i + 1]);
            }
        }
#pragma unroll
        for (int i = 0; i < 16; i++) {
            float u, v; f2unpack(a3[i], u, v);
            u = fmaxf(u, 0.f); v = fmaxf(v, 0.f);
#pragma unroll
            for (int off = 16; off; off >>= 1) {
                u = fmaxf(u, __shfl_xor_sync(0xffffffffu, u, off));
                v = fmaxf(v, __shfl_xor_sync(0xffffffffu, v, off));
            }
            if (lane == 0) {
                O[(q * 32 + 2 * i) * M]     = u;
                O[(q * 32 + 2 * i + 1) * M] = v;
            }
        }
    }
}

// ---------------------------------------------------------------------------
extern "C" void kernel_launch(void* const* d_in, const int* in_sizes, int n_in,
                              void* d_out, int out_size)
{
    const float* feats  = (const float*)d_in[0];
    const float* coords = (const float*)d_in[1];
    const float* W1 = (const float*)d_in[2];
    const float* B1 = (const float*)d_in[3];
    const float* W2 = (const float*)d_in[4];
    const float* B2 = (const float*)d_in[5];
    const float* W3 = (const float*)d_in[6];
    const float* B3 = (const float*)d_in[7];

    float* out     = (float*)d_out;
    float* centers = out + (size_t)BATCH * 128 * M;

    sort_kernel<<<BATCH, 1024>>>(coords);
    prep_kernel<<<(WTOT + 255) / 256, 256>>>(W1, B1, W2, B2, W3, B3);

    fps_kernel<<<BATCH, 512>>>(coords, centers);

    bq_kernel<<<(BATCH * M) / 8, 256>>>(coords, centers);

    const int SMEM1 = 2304 * 4;
    const int SMEM2 = 12544 * 4;
    cudaFuncSetAttribute(mlp1_kernel, cudaFuncAttributeMaxDynamicSharedMemorySize, SMEM1);
    cudaFuncSetAttribute(mlp2_kernel, cudaFuncAttributeMaxDynamicSharedMemorySize, SMEM2);
    mlp1_kernel<<<(BATCH * M) / 8, 256, SMEM1>>>(coords, feats, centers);
    mlp2_kernel<<<(BATCH * M) / 8, 256, SMEM2>>>(out);
}